// round 10
// baseline (speedup 1.0000x reference)
#include <cuda_runtime.h>

#define BATCH 4096
#define TT    512
#define IN    20
#define HID   51
#define NG    204
#define KDIM  71              // HID + IN
#define WROW  204             // interleaved weight row [u*4+g]
#define SPB   16
#define NBLK  (BATCH / SPB)   // 256
#define NTHR  256

// float offsets in dynamic smem
#define OFF_W   0                       // w_il[71][204]
#define OFF_HX  (KDIM * WROW)           // two dup buffers [2][71][32]; rows 0..50 h, 51..70 x
#define HXBUF   (KDIM * 32)             // 2272 floats
#define OFF_W2  (OFF_HX + 2 * HXBUF)    // W_ih2 [4][51]
#define SMEM_FLOATS (OFF_W2 + NG)
#define SMEM_BYTES  (SMEM_FLOATS * 4)   // ~77 KB -> 2 CTAs/SM

typedef unsigned long long ull;

__device__ __forceinline__ ull pack2(float v) {
    ull r; asm("mov.b64 %0, {%1, %1};" : "=l"(r) : "f"(v)); return r;
}
__device__ __forceinline__ ull pack2x(float lo, float hi) {
    ull r; asm("mov.b64 %0, {%1, %2};" : "=l"(r) : "f"(lo), "f"(hi)); return r;
}
__device__ __forceinline__ ull fma2(ull a, ull b, ull c) {
    ull d; asm("fma.rn.f32x2 %0, %1, %2, %3;" : "=l"(d) : "l"(a), "l"(b), "l"(c)); return d;
}
__device__ __forceinline__ void unpack2(ull v, float& lo, float& hi) {
    asm("mov.b64 {%0, %1}, %2;" : "=f"(lo), "=f"(hi) : "l"(v));
}
__device__ __forceinline__ float fsig(float x)  { return __fdividef(1.0f, 1.0f + __expf(-x)); }
__device__ __forceinline__ float ftanh_(float x){ return 1.0f - __fdividef(2.0f, __expf(2.0f * x) + 1.0f); }

__global__ __launch_bounds__(NTHR, 2) void lstm_v10_kernel(
    const float* __restrict__ x,
    const float* __restrict__ W_ih1, const float* __restrict__ W_hh1,
    const float* __restrict__ b_ih1, const float* __restrict__ b_hh1,
    const float* __restrict__ W_ih2, const float* __restrict__ W_hh2,
    const float* __restrict__ b_ih2, const float* __restrict__ b_hh2,
    const float* __restrict__ W_mu,  const float* __restrict__ b_mu,
    const float* __restrict__ W_lv,  const float* __restrict__ b_lv,
    float* __restrict__ out)
{
    extern __shared__ float sm[];
    const int tid = threadIdx.x;
    const int b16 = blockIdx.x * SPB;

    // ---------------- init ----------------
    // interleaved: w_il[k][u*4+g], g: 0=i,1=f,2=g,3=o ; source gate row G = g*51+u
    for (int i = tid; i < KDIM * WROW; i += NTHR) {
        int k = i / WROW, j = i % WROW;
        int u = j >> 2, g = j & 3;
        int G = g * HID + u;
        sm[OFF_W + i] = (k < HID) ? W_hh1[G * HID + k] : W_ih1[G * IN + (k - HID)];
    }
    for (int i = tid; i < HID * 32; i += NTHR) sm[OFF_HX + i] = 0.f;  // h rows of buf0
    for (int i = tid; i < NG; i += NTHR) sm[OFF_W2 + i] = W_ih2[i];   // [4][51]
    for (int i = tid; i < SPB * IN; i += NTHR) {                      // x(0) dup -> buf0
        int s = i / IN, j = i % IN;
        float v = x[((size_t)(b16 + s) * TT) * IN + j];
        sm[OFF_HX + (HID + j) * 32 + 2 * s]     = v;
        sm[OFF_HX + (HID + j) * 32 + 2 * s + 1] = v;
    }

    // ---- roles ----
    const bool is_act = (tid < NG);          // (u, q): u = tid>>2, seqs 4q..4q+3
    const int  u  = tid >> 2;
    const int  q  = tid & 3;
    const bool is_l2 = (tid >= 224 && tid < 240);   // seq = tid-224
    const int  l2s = tid - 224;
    const bool is_xp = (tid >= 240);                // seq = tid-240
    const int  xs = tid - 240;

    ull bif = 0ULL, bgo = 0ULL;
    if (is_act) {
        bif = pack2x(b_ih1[u]         + b_hh1[u],
                     b_ih1[HID + u]   + b_hh1[HID + u]);
        bgo = pack2x(b_ih1[2*HID + u] + b_hh1[2*HID + u],
                     b_ih1[3*HID + u] + b_hh1[3*HID + u]);
    }
    float c1[4] = {0.f, 0.f, 0.f, 0.f};

    float c2 = 0.f, h2 = 0.f, sum_h2 = 0.f;
    float l2b[4] = {0,0,0,0}, l2w[4] = {0,0,0,0};
    if (is_l2) {
        #pragma unroll
        for (int g = 0; g < 4; g++) { l2b[g] = b_ih2[g] + b_hh2[g]; l2w[g] = W_hh2[g]; }
    }
    __syncthreads();

    #pragma unroll 1
    for (int t = 0; t < TT; t++) {
        const float* A = &sm[OFF_HX + (t & 1) * HXBUF];          // h(t-1), x(t)  (dup)
        float*       B = &sm[OFF_HX + ((t + 1) & 1) * HXBUF];    // h(t), x(t+1)  (dup)

        if (is_act) {
            // ---- unit u, 4 seqs, gate-pairs in f32x2 lanes: 3 LDS + 8 FFMA2 per k, 0 MOV ----
            ull aif[4], ago[4];
            #pragma unroll
            for (int s = 0; s < 4; s++) { aif[s] = bif; ago[s] = bgo; }
            const float* wb = &sm[OFF_W + u * 4];
            const float* hb = A + q * 8;
            #pragma unroll
            for (int k = 0; k < KDIM; k++) {
                ulonglong2 wp = *reinterpret_cast<const ulonglong2*>(wb + k * WROW); // {wi,wf},{wg,wo}
                ulonglong2 ha = *reinterpret_cast<const ulonglong2*>(hb + k * 32);     // seqs 4q,4q+1 dup
                ulonglong2 hc = *reinterpret_cast<const ulonglong2*>(hb + k * 32 + 4); // seqs 4q+2,4q+3 dup
                aif[0] = fma2(wp.x, ha.x, aif[0]);  ago[0] = fma2(wp.y, ha.x, ago[0]);
                aif[1] = fma2(wp.x, ha.y, aif[1]);  ago[1] = fma2(wp.y, ha.y, ago[1]);
                aif[2] = fma2(wp.x, hc.x, aif[2]);  ago[2] = fma2(wp.y, hc.x, ago[2]);
                aif[3] = fma2(wp.x, hc.y, aif[3]);  ago[3] = fma2(wp.y, hc.y, ago[3]);
            }
            // ---- in-register activations; write dup h(t) to B ----
            ull hd[4];
            #pragma unroll
            for (int s = 0; s < 4; s++) {
                float gi, gf, gg, go;
                unpack2(aif[s], gi, gf);
                unpack2(ago[s], gg, go);
                float c = fsig(gf) * c1[s] + fsig(gi) * ftanh_(gg);
                c1[s] = c;
                hd[s] = pack2(fsig(go) * ftanh_(c));
            }
            float* Bo = B + u * 32 + q * 8;
            *reinterpret_cast<ulonglong2*>(Bo)     = make_ulonglong2(hd[0], hd[1]);
            *reinterpret_cast<ulonglong2*>(Bo + 4) = make_ulonglong2(hd[2], hd[3]);
        } else if (is_xp) {
            // fire x(t+1) LDGs, then store dup into B rows 51..70
            if (t + 1 < TT) {
                float4 xv[5];
                const float4* xp = reinterpret_cast<const float4*>(
                    &x[((size_t)(b16 + xs) * TT + t + 1) * IN]);
                #pragma unroll
                for (int qq = 0; qq < 5; qq++) xv[qq] = xp[qq];
                #pragma unroll
                for (int qq = 0; qq < 5; qq++) {
                    *reinterpret_cast<ull*>(B + (HID + 4*qq + 0) * 32 + 2 * xs) = pack2(xv[qq].x);
                    *reinterpret_cast<ull*>(B + (HID + 4*qq + 1) * 32 + 2 * xs) = pack2(xv[qq].y);
                    *reinterpret_cast<ull*>(B + (HID + 4*qq + 2) * 32 + 2 * xs) = pack2(xv[qq].z);
                    *reinterpret_cast<ull*>(B + (HID + 4*qq + 3) * 32 + 2 * xs) = pack2(xv[qq].w);
                }
            }
        } else if (is_l2 && t > 0) {
            // layer 2 on h(t-1) in A (dup layout: stride 2)
            float zi = 0.f, zf = 0.f, zg = 0.f, zo = 0.f;
            #pragma unroll
            for (int k = 0; k < HID; k++) {
                float hv = A[k * 32 + 2 * l2s];
                zi += sm[OFF_W2 +          k] * hv;
                zf += sm[OFF_W2 + HID    + k] * hv;
                zg += sm[OFF_W2 + 2*HID  + k] * hv;
                zo += sm[OFF_W2 + 3*HID  + k] * hv;
            }
            float i2 = fsig  (zi + l2b[0] + l2w[0] * h2);
            float f2 = fsig  (zf + l2b[1] + l2w[1] * h2);
            float g2v= ftanh_(zg + l2b[2] + l2w[2] * h2);
            float o2 = fsig  (zo + l2b[3] + l2w[3] * h2);
            c2 = f2 * c2 + i2 * g2v;
            h2 = o2 * ftanh_(c2);
            sum_h2 += h2;
        }
        __syncthreads();
    }

    // ---------- final layer-2 step on h(T-1) + epilogue ----------
    if (is_l2) {
        const float* A = &sm[OFF_HX + (TT & 1) * HXBUF];
        float zi = 0.f, zf = 0.f, zg = 0.f, zo = 0.f;
        #pragma unroll
        for (int k = 0; k < HID; k++) {
            float hv = A[k * 32 + 2 * l2s];
            zi += sm[OFF_W2 +          k] * hv;
            zf += sm[OFF_W2 + HID    + k] * hv;
            zg += sm[OFF_W2 + 2*HID  + k] * hv;
            zo += sm[OFF_W2 + 3*HID  + k] * hv;
        }
        float i2 = fsig  (zi + l2b[0] + l2w[0] * h2);
        float f2 = fsig  (zf + l2b[1] + l2w[1] * h2);
        float g2v= ftanh_(zg + l2b[2] + l2w[2] * h2);
        float o2 = fsig  (zo + l2b[3] + l2w[3] * h2);
        c2 = f2 * c2 + i2 * g2v;
        h2 = o2 * ftanh_(c2);
        sum_h2 += h2;

        float agg = sum_h2 * (1.0f / TT);
        float mu  = W_mu[0] * agg + b_mu[0];
        float lv  = W_lv[0] * agg + b_lv[0];
        float sg  = __expf(0.5f * lv);
        int b = b16 + l2s;
        out[b]           = mu - 1.96f * sg;
        out[BATCH + b]   = mu;
        out[2*BATCH + b] = mu + 1.96f * sg;
        out[3*BATCH + b] = lv;
    }
}

extern "C" void kernel_launch(void* const* d_in, const int* in_sizes, int n_in,
                              void* d_out, int out_size) {
    const float* x     = (const float*)d_in[0];
    const float* W_ih1 = (const float*)d_in[1];
    const float* W_hh1 = (const float*)d_in[2];
    const float* b_ih1 = (const float*)d_in[3];
    const float* b_hh1 = (const float*)d_in[4];
    const float* W_ih2 = (const float*)d_in[5];
    const float* W_hh2 = (const float*)d_in[6];
    const float* b_ih2 = (const float*)d_in[7];
    const float* b_hh2 = (const float*)d_in[8];
    const float* W_mu  = (const float*)d_in[9];
    const float* b_mu  = (const float*)d_in[10];
    const float* W_lv  = (const float*)d_in[11];
    const float* b_lv  = (const float*)d_in[12];
    float* out = (float*)d_out;

    cudaFuncSetAttribute(lstm_v10_kernel,
                         cudaFuncAttributeMaxDynamicSharedMemorySize, SMEM_BYTES);
    lstm_v10_kernel<<<NBLK, NTHR, SMEM_BYTES>>>(x, W_ih1, W_hh1, b_ih1, b_hh1,
                                                W_ih2, W_hh2, b_ih2, b_hh2,
                                                W_mu, b_mu, W_lv, b_lv, out);
}

// round 11
// speedup vs baseline: 1.6956x; 1.6956x over previous
#include <cuda_runtime.h>

#define BATCH 4096
#define TT    512
#define IN    20
#define HID   51
#define NG    204
#define KDIM  71              // HID + IN
#define UPAD  64              // units padded to 64
#define WROW  (UPAD * 4)      // 256 floats per k-row
#define SPB   16              // layout width (max seqs per block)
#define NBLK  296             // 148 SMs x 2 CTAs, 248x14 + 48x13 = 4096 seqs
#define NTHR  160             // 128 matmul + 32 helper

// float offsets in dynamic smem
#define OFF_W   0                         // w_il[71][256]: [k][u*4+g]
#define OFF_HX  (KDIM * WROW)             // two buffers [2][71][16]; rows 0..50 h, 51..70 x
#define HXBUF   (KDIM * 16)               // 1136 floats
#define OFF_W2  (OFF_HX + 2 * HXBUF)      // W_ih2 [4][51]
#define SMEM_FLOATS (OFF_W2 + NG)
#define SMEM_BYTES  (SMEM_FLOATS * 4)     // ~82.6 KB -> 2 CTAs/SM

typedef unsigned long long ull;

__device__ __forceinline__ ull pack2(float v) {
    ull r; asm("mov.b64 %0, {%1, %1};" : "=l"(r) : "f"(v)); return r;
}
__device__ __forceinline__ ull fma2(ull a, ull b, ull c) {
    ull d; asm("fma.rn.f32x2 %0, %1, %2, %3;" : "=l"(d) : "l"(a), "l"(b), "l"(c)); return d;
}
__device__ __forceinline__ void unpack2(ull v, float& lo, float& hi) {
    asm("mov.b64 {%0, %1}, %2;" : "=f"(lo), "=f"(hi) : "l"(v));
}
// MUFU.TANH-based activations: tanh = 1 MUFU; sigmoid = 0.5*tanh(x/2)+0.5
__device__ __forceinline__ float tanh_a(float x) {
    float y; asm("tanh.approx.f32 %0, %1;" : "=f"(y) : "f"(x)); return y;
}
__device__ __forceinline__ float fsig(float x)   { return fmaf(0.5f, tanh_a(0.5f * x), 0.5f); }
__device__ __forceinline__ float ftanh_(float x) { return tanh_a(x); }

__global__ __launch_bounds__(NTHR, 2) void lstm_v11_kernel(
    const float* __restrict__ x,
    const float* __restrict__ W_ih1, const float* __restrict__ W_hh1,
    const float* __restrict__ b_ih1, const float* __restrict__ b_hh1,
    const float* __restrict__ W_ih2, const float* __restrict__ W_hh2,
    const float* __restrict__ b_ih2, const float* __restrict__ b_hh2,
    const float* __restrict__ W_mu,  const float* __restrict__ b_mu,
    const float* __restrict__ W_lv,  const float* __restrict__ b_lv,
    float* __restrict__ out)
{
    extern __shared__ float sm[];
    const int tid = threadIdx.x;

    // balanced seq assignment: first 248 CTAs take 14 seqs, last 48 take 13
    int start, cnt;
    if (blockIdx.x < 248) { start = blockIdx.x * 14;              cnt = 14; }
    else                  { start = 3472 + (blockIdx.x - 248)*13; cnt = 13; }

    // ---------------- init ----------------
    // interleaved transpose: w_il[k][u*4+g], gate order g = i,f,g,o (G = g*51+u)
    for (int i = tid; i < KDIM * WROW; i += NTHR) {
        int k = i >> 8, j = i & 255;
        int u = j >> 2, g = j & 3;
        float v = 0.f;
        if (u < HID) {
            int G = g * HID + u;
            v = (k < HID) ? W_hh1[G * HID + k] : W_ih1[G * IN + (k - HID)];
        }
        sm[OFF_W + i] = v;
    }
    for (int i = tid; i < 2 * HXBUF; i += NTHR) sm[OFF_HX + i] = 0.f;  // zero both buffers
    for (int i = tid; i < NG; i += NTHR) sm[OFF_W2 + i] = W_ih2[i];
    __syncthreads();
    if (tid < cnt) {   // x(0) -> buf0 rows 51..70
        const float4* xp = reinterpret_cast<const float4*>(&x[((size_t)(start + tid) * TT) * IN]);
        #pragma unroll
        for (int q = 0; q < 5; q++) {
            float4 v = xp[q];
            sm[OFF_HX + (HID + 4*q + 0) * 16 + tid] = v.x;
            sm[OFF_HX + (HID + 4*q + 1) * 16 + tid] = v.y;
            sm[OFF_HX + (HID + 4*q + 2) * 16 + tid] = v.z;
            sm[OFF_HX + (HID + 4*q + 3) * 16 + tid] = v.w;
        }
    }

    // matmul threads 0..127: unit u = tid>>1, seq-half sh8 = (tid&1)*8
    const int u   = tid >> 1;
    const int sh8 = (tid & 1) << 3;
    ull bp[4] = {0ULL, 0ULL, 0ULL, 0ULL};
    if (tid < 128 && u < HID) {
        #pragma unroll
        for (int g = 0; g < 4; g++)
            bp[g] = pack2(b_ih1[g * HID + u] + b_hh1[g * HID + u]);
    }
    float c1[8] = {0.f,0.f,0.f,0.f,0.f,0.f,0.f,0.f};

    // helper threads 128..143: seq hs; x prefetch + layer 2
    const int hs = tid - 128;
    const bool hlp = (hs >= 0 && hs < cnt);
    float c2 = 0.f, h2 = 0.f, sum_h2 = 0.f;
    float l2b[4] = {0,0,0,0}, l2w[4] = {0,0,0,0};
    if (hlp) {
        #pragma unroll
        for (int g = 0; g < 4; g++) { l2b[g] = b_ih2[g] + b_hh2[g]; l2w[g] = W_hh2[g]; }
    }
    __syncthreads();

    #pragma unroll 1
    for (int t = 0; t < TT; t++) {
        const float* A = &sm[OFF_HX + (t & 1) * HXBUF];          // h(t-1), x(t)
        float*       B = &sm[OFF_HX + ((t + 1) & 1) * HXBUF];    // h(t), x(t+1)

        if (tid < 128) {
            // ---- gates for unit u, 8 seqs, all 4 gates in registers ----
            ull a[16];   // a[g*4+p], p -> seqs (2p, 2p+1)
            #pragma unroll
            for (int g = 0; g < 4; g++) {
                a[g*4+0] = bp[g]; a[g*4+1] = bp[g]; a[g*4+2] = bp[g]; a[g*4+3] = bp[g];
            }
            const float* wb = &sm[OFF_W + u * 4];
            const float* hb = A + sh8;
            #pragma unroll
            for (int k = 0; k < KDIM; k++) {
                float4 w4 = *reinterpret_cast<const float4*>(wb + k * WROW);
                ulonglong2 h0 = *reinterpret_cast<const ulonglong2*>(hb + k * 16);
                ulonglong2 h1 = *reinterpret_cast<const ulonglong2*>(hb + k * 16 + 4);
                ull wi = pack2(w4.x), wf = pack2(w4.y), wg = pack2(w4.z), wo = pack2(w4.w);
                a[0]  = fma2(wi, h0.x, a[0]);  a[1]  = fma2(wi, h0.y, a[1]);
                a[2]  = fma2(wi, h1.x, a[2]);  a[3]  = fma2(wi, h1.y, a[3]);
                a[4]  = fma2(wf, h0.x, a[4]);  a[5]  = fma2(wf, h0.y, a[5]);
                a[6]  = fma2(wf, h1.x, a[6]);  a[7]  = fma2(wf, h1.y, a[7]);
                a[8]  = fma2(wg, h0.x, a[8]);  a[9]  = fma2(wg, h0.y, a[9]);
                a[10] = fma2(wg, h1.x, a[10]); a[11] = fma2(wg, h1.y, a[11]);
                a[12] = fma2(wo, h0.x, a[12]); a[13] = fma2(wo, h0.y, a[13]);
                a[14] = fma2(wo, h1.x, a[14]); a[15] = fma2(wo, h1.y, a[15]);
            }
            // ---- in-register activations, write h(t) to B ----
            if (u < HID) {
                float hv[8];
                #pragma unroll
                for (int p = 0; p < 4; p++) {
                    float i0,i1,f0,f1,g0,g1,o0,o1;
                    unpack2(a[p],      i0, i1);
                    unpack2(a[4 + p],  f0, f1);
                    unpack2(a[8 + p],  g0, g1);
                    unpack2(a[12 + p], o0, o1);
                    float ca = fsig(f0) * c1[2*p]     + fsig(i0) * ftanh_(g0);
                    c1[2*p] = ca;     hv[2*p]     = fsig(o0) * ftanh_(ca);
                    float cb = fsig(f1) * c1[2*p + 1] + fsig(i1) * ftanh_(g1);
                    c1[2*p+1] = cb;   hv[2*p + 1] = fsig(o1) * ftanh_(cb);
                }
                *reinterpret_cast<float4*>(B + u * 16 + sh8)     = make_float4(hv[0], hv[1], hv[2], hv[3]);
                *reinterpret_cast<float4*>(B + u * 16 + sh8 + 4) = make_float4(hv[4], hv[5], hv[6], hv[7]);
            }
        } else if (hlp) {
            // fire x(t+1) loads early
            float4 xv[5];
            if (t + 1 < TT) {
                const float4* xp = reinterpret_cast<const float4*>(
                    &x[((size_t)(start + hs) * TT + t + 1) * IN]);
                #pragma unroll
                for (int q = 0; q < 5; q++) xv[q] = xp[q];
            }
            // layer 2 on h(t-1) in A
            if (t > 0) {
                float zi = 0.f, zf = 0.f, zg = 0.f, zo = 0.f;
                #pragma unroll
                for (int k = 0; k < HID; k++) {
                    float hvv = A[k * 16 + hs];
                    zi += sm[OFF_W2 +          k] * hvv;
                    zf += sm[OFF_W2 + HID    + k] * hvv;
                    zg += sm[OFF_W2 + 2*HID  + k] * hvv;
                    zo += sm[OFF_W2 + 3*HID  + k] * hvv;
                }
                float i2 = fsig  (zi + l2b[0] + l2w[0] * h2);
                float f2 = fsig  (zf + l2b[1] + l2w[1] * h2);
                float g2v= ftanh_(zg + l2b[2] + l2w[2] * h2);
                float o2 = fsig  (zo + l2b[3] + l2w[3] * h2);
                c2 = f2 * c2 + i2 * g2v;
                h2 = o2 * ftanh_(c2);
                sum_h2 += h2;
            }
            // store x(t+1) into B rows 51..70
            if (t + 1 < TT) {
                #pragma unroll
                for (int q = 0; q < 5; q++) {
                    B[(HID + 4*q + 0) * 16 + hs] = xv[q].x;
                    B[(HID + 4*q + 1) * 16 + hs] = xv[q].y;
                    B[(HID + 4*q + 2) * 16 + hs] = xv[q].z;
                    B[(HID + 4*q + 3) * 16 + hs] = xv[q].w;
                }
            }
        }
        __syncthreads();
    }

    // ---------- final layer-2 step on h(T-1) + epilogue ----------
    if (hlp) {
        const float* A = &sm[OFF_HX + (TT & 1) * HXBUF];
        float zi = 0.f, zf = 0.f, zg = 0.f, zo = 0.f;
        #pragma unroll
        for (int k = 0; k < HID; k++) {
            float hvv = A[k * 16 + hs];
            zi += sm[OFF_W2 +          k] * hvv;
            zf += sm[OFF_W2 + HID    + k] * hvv;
            zg += sm[OFF_W2 + 2*HID  + k] * hvv;
            zo += sm[OFF_W2 + 3*HID  + k] * hvv;
        }
        float i2 = fsig  (zi + l2b[0] + l2w[0] * h2);
        float f2 = fsig  (zf + l2b[1] + l2w[1] * h2);
        float g2v= ftanh_(zg + l2b[2] + l2w[2] * h2);
        float o2 = fsig  (zo + l2b[3] + l2w[3] * h2);
        c2 = f2 * c2 + i2 * g2v;
        h2 = o2 * ftanh_(c2);
        sum_h2 += h2;

        float agg = sum_h2 * (1.0f / TT);
        float mu  = W_mu[0] * agg + b_mu[0];
        float lv  = W_lv[0] * agg + b_lv[0];
        float sg  = __expf(0.5f * lv);
        int b = start + hs;
        out[b]           = mu - 1.96f * sg;
        out[BATCH + b]   = mu;
        out[2*BATCH + b] = mu + 1.96f * sg;
        out[3*BATCH + b] = lv;
    }
}

extern "C" void kernel_launch(void* const* d_in, const int* in_sizes, int n_in,
                              void* d_out, int out_size) {
    const float* x     = (const float*)d_in[0];
    const float* W_ih1 = (const float*)d_in[1];
    const float* W_hh1 = (const float*)d_in[2];
    const float* b_ih1 = (const float*)d_in[3];
    const float* b_hh1 = (const float*)d_in[4];
    const float* W_ih2 = (const float*)d_in[5];
    const float* W_hh2 = (const float*)d_in[6];
    const float* b_ih2 = (const float*)d_in[7];
    const float* b_hh2 = (const float*)d_in[8];
    const float* W_mu  = (const float*)d_in[9];
    const float* b_mu  = (const float*)d_in[10];
    const float* W_lv  = (const float*)d_in[11];
    const float* b_lv  = (const float*)d_in[12];
    float* out = (float*)d_out;

    cudaFuncSetAttribute(lstm_v11_kernel,
                         cudaFuncAttributeMaxDynamicSharedMemorySize, SMEM_BYTES);
    lstm_v11_kernel<<<NBLK, NTHR, SMEM_BYTES>>>(x, W_ih1, W_hh1, b_ih1, b_hh1,
                                                W_ih2, W_hh2, b_ih2, b_hh2,
                                                W_mu, b_mu, W_lv, b_lv, out);
}